// round 3
// baseline (speedup 1.0000x reference)
#include <cuda_runtime.h>
#include <cstdint>

// out[b][o][i][l] = white_table[o][i][ x[b][i][o][l] ]
// B=8, O=I=64, L=2048. L contiguous on both sides -> fully coalesced vec4.
// One block per (o,i): LUT in smem once; stream 8 batches with 4-deep
// explicit load batching (MLP=4) + streaming cache hints.

#define B_DIM 8
#define CH 64
#define L_DIM 2048
#define THREADS 256
#define VPB (L_DIM / 4 / THREADS)   // int4 per thread per batch = 2

__global__ __launch_bounds__(THREADS) void white_transpose_kernel(
    const int* __restrict__ x,
    const float* __restrict__ table,
    float* __restrict__ out)
{
    const int idx = blockIdx.x;          // 0..4095
    const int i = idx & (CH - 1);
    const int o = idx >> 6;

    __shared__ float lut[256];
    const float* t = table + ((o * CH + i) << 8);
    if (threadIdx.x < 256) lut[threadIdx.x] = t[threadIdx.x];
    __syncthreads();

    const size_t bstride4 = (size_t)CH * CH * (L_DIM / 4);  // int4 units per batch
    const int4* __restrict__ xin =
        reinterpret_cast<const int4*>(x) + (size_t)(i * CH + o) * (L_DIM / 4);
    float4* __restrict__ op =
        reinterpret_cast<float4*>(out) + (size_t)(o * CH + i) * (L_DIM / 4);

    // 16 int4 per thread total (8 batches x 2). Process in 4 groups of 4
    // independent loads: LDGx4 -> LDSx16 -> STGx4.
    #pragma unroll
    for (int g = 0; g < 4; g++) {
        const int b0 = g * 2;           // two batches per group, 2 vecs each
        const size_t base0 = b0 * bstride4;
        const size_t base1 = (b0 + 1) * bstride4;
        const int vi0 = threadIdx.x;
        const int vi1 = THREADS + threadIdx.x;

        int4 a0 = __ldcs(xin + base0 + vi0);
        int4 a1 = __ldcs(xin + base0 + vi1);
        int4 a2 = __ldcs(xin + base1 + vi0);
        int4 a3 = __ldcs(xin + base1 + vi1);

        float4 r0, r1, r2, r3;
        r0.x = lut[a0.x]; r0.y = lut[a0.y]; r0.z = lut[a0.z]; r0.w = lut[a0.w];
        r1.x = lut[a1.x]; r1.y = lut[a1.y]; r1.z = lut[a1.z]; r1.w = lut[a1.w];
        r2.x = lut[a2.x]; r2.y = lut[a2.y]; r2.z = lut[a2.z]; r2.w = lut[a2.w];
        r3.x = lut[a3.x]; r3.y = lut[a3.y]; r3.z = lut[a3.z]; r3.w = lut[a3.w];

        __stcs(op + base0 + vi0, r0);
        __stcs(op + base0 + vi1, r1);
        __stcs(op + base1 + vi0, r2);
        __stcs(op + base1 + vi1, r3);
    }
}

extern "C" void kernel_launch(void* const* d_in, const int* in_sizes, int n_in,
                              void* d_out, int out_size)
{
    const int* x = (const int*)d_in[0];          // [8, 64, 64, 2048] int32
    const float* table = (const float*)d_in[1];  // [64, 64, 256] float32
    float* out = (float*)d_out;                  // [8, 64, 64, 2048] float32

    const int grid = CH * CH;  // 4096 blocks, one per (o,i)
    white_transpose_kernel<<<grid, THREADS>>>(x, table, out);
}